// round 2
// baseline (speedup 1.0000x reference)
#include <cuda_runtime.h>
#include <math.h>

// Scalar constants derived from para_ham_unknown (computed on device, kernel 1)
__device__ float g_r;     // sqrt(max(rsq,1e-30))
__device__ float g_rsq;   // a^2 + |z|^2
__device__ float g_c;     // (Re z)^2
__device__ double g_acc;  // loss accumulator

#define DT_F 0.1f               // TIME_DURATION / NUM_SEGMENT
#define NSEG 10

__global__ void prep_kernel(const float* __restrict__ p) {
    // p = para_ham_unknown row-major: x00 x01 x10 x11
    float x00 = p[0], x01 = p[1], x10 = p[2], x11 = p[3];
    float a   = 0.5f * (x00 - x11);                 // H0 diagonal (real)
    float rez = 0.5f + 0.5f * (x01 + x10);          // Re(H0[0][1]) incl. model 0.5
    float imz = 0.5f * (x01 - x10);                 // Im(H0[0][1])
    float rsq = a * a + rez * rez + imz * imz;      // tr(H0 H0).real / 2
    g_rsq = rsq;
    g_r   = sqrtf(fmaxf(rsq, 1e-30f));
    g_c   = rez * rez;                              // (2*Re z)^2 / 4
    g_acc = 0.0;
}

// Each thread processes TWO rows (80 bytes = 5 x float4, perfectly aligned).
__global__ void __launch_bounds__(256) main_kernel(
    const float* __restrict__ omega,
    const float* __restrict__ infd,
    int npairs)
{
    const int t = blockIdx.x * blockDim.x + threadIdx.x;

    const float r   = g_r;
    const float rsq = g_rsq;
    const float c   = g_c;

    double local = 0.0;
    if (t < npairs) {
        const float4* om4 = reinterpret_cast<const float4*>(omega) + (size_t)t * 5;
        float4 v0 = om4[0];
        float4 v1 = om4[1];
        float4 v2 = om4[2];
        float4 v3 = om4[3];
        float4 v4 = om4[4];

        // row 2t   : v0.xyzw v1.xyzw v2.xy
        // row 2t+1 : v2.zw v3.xyzw v4.xyzw
        float s0 = ((v0.x + v0.y) + (v0.z + v0.w))
                 + ((v1.x + v1.y) + (v1.z + v1.w))
                 + (v2.x + v2.y);
        float s1 = (v2.z + v2.w)
                 + ((v3.x + v3.y) + (v3.z + v3.w))
                 + ((v4.x + v4.y) + (v4.z + v4.w));

        float2 f = reinterpret_cast<const float2*>(infd)[t];

        // row 0
        {
            float phi   = DT_F * s0;
            float theta = phi * r;
            float sinc  = (rsq > 1e-24f) ? (sinf(theta) / r) : phi;
            float infid = 1.0f - sinc * sinc * c;
            float d     = f.x - infid;
            local += (double)(d * d);
        }
        // row 1
        {
            float phi   = DT_F * s1;
            float theta = phi * r;
            float sinc  = (rsq > 1e-24f) ? (sinf(theta) / r) : phi;
            float infid = 1.0f - sinc * sinc * c;
            float d     = f.y - infid;
            local += (double)(d * d);
        }
    }

    // warp reduction
    #pragma unroll
    for (int off = 16; off > 0; off >>= 1)
        local += __shfl_down_sync(0xFFFFFFFFu, local, off);

    __shared__ double warp_sums[8];
    int lane = threadIdx.x & 31;
    int wid  = threadIdx.x >> 5;
    if (lane == 0) warp_sums[wid] = local;
    __syncthreads();

    if (wid == 0) {
        double v = (lane < (blockDim.x >> 5)) ? warp_sums[lane] : 0.0;
        #pragma unroll
        for (int off = 4; off > 0; off >>= 1)
            v += __shfl_down_sync(0xFFFFFFFFu, v, off);
        if (lane == 0)
            atomicAdd(&g_acc, v);
    }
}

__global__ void finalize_kernel(float* __restrict__ out, int ndata) {
    out[0] = (float)(g_acc / (double)ndata);
}

extern "C" void kernel_launch(void* const* d_in, const int* in_sizes, int n_in,
                              void* d_out, int out_size) {
    const float* para  = (const float*)d_in[0];   // 4 elements
    const float* omega = (const float*)d_in[1];   // NUM_DATA * 10
    const float* infd  = (const float*)d_in[2];   // NUM_DATA
    float* out = (float*)d_out;

    int ndata  = in_sizes[2];
    int npairs = ndata / 2;

    prep_kernel<<<1, 1>>>(para);

    int threads = 256;
    int blocks  = (npairs + threads - 1) / threads;
    main_kernel<<<blocks, threads>>>(omega, infd, npairs);

    finalize_kernel<<<1, 1>>>(out, ndata);
}